// round 15
// baseline (speedup 1.0000x reference)
#include <cuda_runtime.h>

// CRF loss, T=512, B=1024, K=48. R15 = R11 (fwd/bwd split, LPT, 296x128 at
// 2 blocks/SM) but each worker warp runs TWO independent half-jobs
// (adjacent LPT ranks -> near-equal lengths; same direction -> shared etp
// table). The two chains' LDS/FMA streams interleave in one warp to fill
// chain-latency bubbles; one syncwarp per step covers both. Step body
// unchanged: linear space, smem ping-pong {P_2i,P_2i+1}, 12 broadcast
// LDS.128 + 48 fma.rn.f32x2 / 8 accumulators, exact power-of-2 renorm
// every 2 steps folded into ex2.

#define TT 512
#define BB 1024
#define KK 48
#define NBLKW 296
#define START_TAG 46
#define STOP_TAG  47
#define LN2F  0.6931471805599453f
#define LOG2E 1.4426950408889634f
#define PFD 4

__device__ float g_partial[BB];
__device__ float g_fwdv[BB * KK];
__device__ float g_bwdv[BB * KK];
__device__ float g_gold[BB];
__device__ int   g_cf[BB];
__device__ int   g_cb[BB];
__device__ int   g_flag[BB];
__device__ int   g_order[BB];      // rank -> batch (longest first)
__device__ int   g_next_f, g_next_b, g_done;

__device__ __forceinline__ unsigned long long pack2(float lo, float hi) {
    unsigned long long r;
    asm("mov.b64 %0, {%1, %2};" : "=l"(r) : "f"(lo), "f"(hi));
    return r;
}
__device__ __forceinline__ void unpack2(unsigned long long v, float& lo, float& hi) {
    asm("mov.b64 {%0, %1}, %2;" : "=f"(lo), "=f"(hi) : "l"(v));
}
__device__ __forceinline__ unsigned long long fma2(unsigned long long a,
                                                   unsigned long long b,
                                                   unsigned long long c) {
    unsigned long long d;
    asm("fma.rn.f32x2 %0, %1, %2, %3;" : "=l"(d) : "l"(a), "l"(b), "l"(c));
    return d;
}
__device__ __forceinline__ unsigned long long add2(unsigned long long a,
                                                   unsigned long long b) {
    unsigned long long d;
    asm("add.rn.f32x2 %0, %1, %2;" : "=l"(d) : "l"(a), "l"(b));
    return d;
}
__device__ __forceinline__ float ex2f(float x) {
    float r;
    asm("ex2.approx.f32 %0, %1;" : "=f"(r) : "f"(x));
    return r;
}

// ---------- pre-pass: longest-first rank + counter/flag reset --------------
__global__ void perm_kernel(const int* __restrict__ lengths) {
    __shared__ int s_len[BB];
    const int tid = threadIdx.x;
    const int b = blockIdx.x * 512 + tid;
    s_len[tid] = lengths[tid];
    s_len[tid + 512] = lengths[tid + 512];
    __syncthreads();

    const int lb = s_len[b];
    int k = 0;
    #pragma unroll 8
    for (int j = 0; j < BB; j++) {
        int lj = s_len[j];
        k += (lj > lb) || (lj == lb && j < b);
    }
    g_order[k] = b;
    g_flag[b] = 0;
    if (b == 0) { g_next_f = 0; g_next_b = 0; g_done = 0; }
}

// ---------- one recursion step (Cint passed explicitly) --------------------
#define STEP(PIN, POUT, FC, CINT, RENORM)                                    \
    do {                                                                     \
        const ulonglong2* pv = (const ulonglong2*)(PIN);                     \
        ulonglong2 e0 = pv[0];                                               \
        unsigned long long c0 = fma2(e0.x, etp0[0], 0ull);                   \
        unsigned long long c2 = fma2(e0.y, etp0[1], 0ull);                   \
        unsigned long long c4 = fma2(e0.x, etp1[0], 0ull);                   \
        unsigned long long c6 = fma2(e0.y, etp1[1], 0ull);                   \
        unsigned long long c1 = 0ull, c3 = 0ull, c5 = 0ull, c7 = 0ull;       \
        _Pragma("unroll")                                                    \
        for (int q = 1; q < 12; q++) {                                       \
            ulonglong2 e = pv[q];                                            \
            if (q & 1) {                                                     \
                c1 = fma2(e.x, etp0[2*q],     c1);                           \
                c3 = fma2(e.y, etp0[2*q + 1], c3);                           \
                c5 = fma2(e.x, etp1[2*q],     c5);                           \
                c7 = fma2(e.y, etp1[2*q + 1], c7);                           \
            } else {                                                         \
                c0 = fma2(e.x, etp0[2*q],     c0);                           \
                c2 = fma2(e.y, etp0[2*q + 1], c2);                           \
                c4 = fma2(e.x, etp1[2*q],     c4);                           \
                c6 = fma2(e.y, etp1[2*q + 1], c6);                           \
            }                                                                \
        }                                                                    \
        unsigned long long sum0 = add2(add2(c0, c1), add2(c2, c3));          \
        unsigned long long sum1 = add2(add2(c4, c5), add2(c6, c7));          \
        float fpe = 0.0f;                                                    \
        if (RENORM) {                                                        \
            unsigned int pexp = ((unsigned)e0.x) >> 23;                      \
            int pe = (pexp - 1u < 254u) ? (int)pexp - 127 : 0;               \
            CINT += pe;                                                      \
            fpe = (float)(-pe);                                              \
        }                                                                    \
        float m0 = ex2f(fmaf((FC).x, LOG2E, fpe));                           \
        float m1 = ex2f(fmaf((FC).y, LOG2E, fpe));                           \
        float l0, h0, l1, h1;                                                \
        unpack2(sum0, l0, h0);                                               \
        unpack2(sum1, l1, h1);                                               \
        (POUT)[lane] = make_float2((l0 + h0) * m0, (l1 + h1) * m1);          \
    } while (0)

// second finisher: combine halves; last batch -> deterministic final sum
#define COMBINE(BATCH)                                                       \
    do {                                                                     \
        __threadfence();                                                     \
        float v = 0.0f;                                                      \
        if (act) {                                                           \
            float2 pfv = *(const float2*)&g_fwdv[(BATCH) * KK + sc];         \
            float2 bbv = *(const float2*)&g_bwdv[(BATCH) * KK + sc];         \
            v = pfv.x * bbv.x + pfv.y * bbv.y;                               \
        }                                                                    \
        _Pragma("unroll")                                                    \
        for (int o = 16; o; o >>= 1) v += __shfl_xor_sync(~0u, v, o);        \
        float logz = (float)(g_cf[BATCH] + g_cb[BATCH]) * LN2F + __logf(v);  \
        int l2 = 0;                                                          \
        if (lane == 0) {                                                     \
            g_partial[BATCH] = logz - g_gold[BATCH];                         \
            __threadfence();                                                 \
            int p2 = atomicAdd(&g_done, 1);                                  \
            l2 = (p2 == BB - 1);                                             \
        }                                                                    \
        l2 = __shfl_sync(~0u, l2, 0);                                        \
        if (l2) {                                                            \
            __threadfence();                                                 \
            float a = 0.0f;                                                  \
            _Pragma("unroll")                                                \
            for (int i = 0; i < BB / 32; i++)                                \
                a += g_partial[lane + i * 32];                               \
            _Pragma("unroll")                                                \
            for (int o = 16; o; o >>= 1) a += __shfl_xor_sync(~0u, a, o);    \
            if (lane == 0) out[0] = a;                                       \
        }                                                                    \
    } while (0)

__global__ void __launch_bounds__(128, 2) crf_kernel(
    const float* __restrict__ feats,
    const float* __restrict__ trans,
    const int*   __restrict__ tags,
    const int*   __restrict__ lengths,
    float*       __restrict__ out)
{
    __shared__ __align__(16) float2 s_pw[4][2][2][32];  // [wid][chain][buf]
    __shared__ float s_trans[KK * KK];

    const int tid  = threadIdx.x;
    const int wid  = tid >> 5;
    const int lane = tid & 31;
    const bool act = (lane < 24);
    const int sc = act ? 2 * lane : 44;
    const int s0 = sc, s1 = sc + 1;
    const bool is_fwd = (wid < 2);

    for (int i = tid; i < KK * KK; i += 128) s_trans[i] = trans[i];
    __syncthreads();

    float2 (*spA)[32] = s_pw[wid][0];
    float2 (*spB)[32] = s_pw[wid][1];

    // shared table for BOTH chains (same direction)
    unsigned long long etp0[24], etp1[24];
    #pragma unroll
    for (int i = 0; i < 24; i++) {
        if (is_fwd) {
            etp0[i] = pack2(__expf(s_trans[s0 * KK + 2*i]),
                            __expf(s_trans[s0 * KK + 2*i + 1]));
            etp1[i] = pack2(__expf(s_trans[s1 * KK + 2*i]),
                            __expf(s_trans[s1 * KK + 2*i + 1]));
        } else {
            etp0[i] = pack2(__expf(s_trans[(2*i) * KK + s0]),
                            __expf(s_trans[(2*i + 1) * KK + s0]));
            etp1[i] = pack2(__expf(s_trans[(2*i) * KK + s1]),
                            __expf(s_trans[(2*i + 1) * KK + s1]));
        }
    }
    const float st0 = __expf(s_trans[STOP_TAG * KK + s0]);
    const float st1 = __expf(s_trans[STOP_TAG * KK + s1]);
    const long long FS = (long long)BB * KK;
    const long long pstep = (FS / 2) * (is_fwd ? 1 : -1);
    int* qn = is_fwd ? &g_next_f : &g_next_b;

    for (;;) {
        int j = 0;
        if (lane == 0) j = atomicAdd(qn, 2);
        j = __shfl_sync(~0u, j, 0);
        if (j >= BB) break;
        const bool hasB = (j + 1 < BB);
        const int bA   = __ldg(&g_order[j]);
        const int bB   = hasB ? __ldg(&g_order[j + 1]) : bA;
        const int lenA = __ldg(lengths + bA);
        const int lenB = __ldg(lengths + bB);
        const int mA = lenA >> 1, mB = lenB >> 1;
        const int nA = is_fwd ? mA : (lenA - mA);
        const int nB = hasB ? (is_fwd ? mB : (lenB - mB)) : 0;
        const float* fbA = feats + (long long)bA * KK;
        const float* fbB = feats + (long long)bB * KK;

        int CintA = 0, CintB = 0;
        float2 a1 = {0,0}, a2 = {0,0}, a3 = {0,0}, a4 = {0,0};
        float2 b1 = {0,0}, b2 = {0,0}, b3 = {0,0}, b4 = {0,0};
        const float2 *pfA, *pfB;
        int preA, preB;

        if (is_fwd) {
            spA[0][lane] = (lane == 23) ? make_float2(1.0f, 0.0f)
                                        : make_float2(0.0f, 0.0f);
            spA[1][lane] = make_float2(0.0f, 0.0f);
            spB[0][lane] = (lane == 23) ? make_float2(1.0f, 0.0f)
                                        : make_float2(0.0f, 0.0f);
            spB[1][lane] = make_float2(0.0f, 0.0f);
            a1 = __ldg((const float2*)(fbA + sc));      // t=0, len>=1
            if (1 < nA) a2 = __ldg((const float2*)(fbA + 1 * FS + sc));
            if (2 < nA) a3 = __ldg((const float2*)(fbA + 2 * FS + sc));
            if (3 < nA) a4 = __ldg((const float2*)(fbA + 3 * FS + sc));
            if (hasB) {
                b1 = __ldg((const float2*)(fbB + sc));
                if (1 < nB) b2 = __ldg((const float2*)(fbB + 1 * FS + sc));
                if (2 < nB) b3 = __ldg((const float2*)(fbB + 2 * FS + sc));
                if (3 < nB) b4 = __ldg((const float2*)(fbB + 3 * FS + sc));
            }
            pfA = (const float2*)(fbA + sc) + (long long)PFD * (FS / 2);
            pfB = (const float2*)(fbB + sc) + (long long)PFD * (FS / 2);
            preA = nA - PFD;
            preB = nB - PFD;
        } else {
            float2 f0 = __ldg((const float2*)(fbA + (long long)(lenA - 1) * FS + sc));
            spA[0][lane] = make_float2(st0 * ex2f(f0.x * LOG2E),
                                       st1 * ex2f(f0.y * LOG2E));
            spA[1][lane] = make_float2(0.0f, 0.0f);
            const float2* fA2 = (const float2*)(fbA + sc);
            if (0 < nA - 1) a1 = __ldg(fA2 + (long long)(lenA - 2) * (FS / 2));
            if (1 < nA - 1) a2 = __ldg(fA2 + (long long)(lenA - 3) * (FS / 2));
            if (2 < nA - 1) a3 = __ldg(fA2 + (long long)(lenA - 4) * (FS / 2));
            if (3 < nA - 1) a4 = __ldg(fA2 + (long long)(lenA - 5) * (FS / 2));
            pfA = fA2 + (long long)(lenA - 2 - PFD) * (FS / 2);
            preA = nA - 1 - PFD;
            if (hasB) {
                float2 g0 = __ldg((const float2*)(fbB + (long long)(lenB - 1) * FS + sc));
                spB[0][lane] = make_float2(st0 * ex2f(g0.x * LOG2E),
                                           st1 * ex2f(g0.y * LOG2E));
                spB[1][lane] = make_float2(0.0f, 0.0f);
                const float2* fB2 = (const float2*)(fbB + sc);
                if (0 < nB - 1) b1 = __ldg(fB2 + (long long)(lenB - 2) * (FS / 2));
                if (1 < nB - 1) b2 = __ldg(fB2 + (long long)(lenB - 3) * (FS / 2));
                if (2 < nB - 1) b3 = __ldg(fB2 + (long long)(lenB - 4) * (FS / 2));
                if (3 < nB - 1) b4 = __ldg(fB2 + (long long)(lenB - 5) * (FS / 2));
                pfB = fB2 + (long long)(lenB - 2 - PFD) * (FS / 2);
            } else {
                pfB = (const float2*)(fbB + sc);
            }
            preB = nB - 1 - PFD;
        }
        __syncwarp();

        // dual-chain mainloop, unrolled x2 over ping-pong
        const int nmax = nA > nB ? nA : nB;
        int t = 0;
        #pragma unroll 1
        while (t + 1 < nmax) {
            {
                float2 fcA = a1; a1 = a2; a2 = a3; a3 = a4;
                a4 = (t < preA) ? __ldg(pfA) : make_float2(0.0f, 0.0f);
                pfA += pstep;
                float2 fcB = b1; b1 = b2; b2 = b3; b3 = b4;
                b4 = (t < preB) ? __ldg(pfB) : make_float2(0.0f, 0.0f);
                pfB += pstep;
                if (t < nA) STEP(spA[0], spA[1], fcA, CintA, true);
                if (t < nB) STEP(spB[0], spB[1], fcB, CintB, true);
            }
            __syncwarp();
            {
                float2 fcA = a1; a1 = a2; a2 = a3; a3 = a4;
                a4 = (t + 1 < preA) ? __ldg(pfA) : make_float2(0.0f, 0.0f);
                pfA += pstep;
                float2 fcB = b1; b1 = b2; b2 = b3; b3 = b4;
                b4 = (t + 1 < preB) ? __ldg(pfB) : make_float2(0.0f, 0.0f);
                pfB += pstep;
                if (t + 1 < nA) STEP(spA[1], spA[0], fcA, CintA, false);
                if (t + 1 < nB) STEP(spB[1], spB[0], fcB, CintB, false);
            }
            __syncwarp();
            t += 2;
        }
        if (t < nmax) {
            float2 fcA = a1;
            float2 fcB = b1;
            if (t < nA) STEP(spA[0], spA[1], fcA, CintA, true);
            if (t < nB) STEP(spB[0], spB[1], fcB, CintB, true);
            __syncwarp();
        }

        // publish meeting vectors
        if (act) {
            float* gv = is_fwd ? g_fwdv : g_bwdv;
            *(float2*)&gv[bA * KK + sc] = spA[nA & 1][lane];
            if (hasB) *(float2*)&gv[bB * KK + sc] = spB[nB & 1][lane];
        }

        // epilogue chain A
        if (is_fwd) {
            const int* tg = tags + bA * TT;
            float g = 0.0f;
            for (int q = lane; q < lenA; q += 32) {
                int nxt = __ldg(tg + q);
                int prv = (q == 0) ? START_TAG : __ldg(tg + q - 1);
                g += s_trans[nxt * KK + prv] + __ldg(fbA + (long long)q * FS + nxt);
            }
            #pragma unroll
            for (int o = 16; o; o >>= 1) g += __shfl_xor_sync(~0u, g, o);
            if (lane == 0) {
                g_gold[bA] = g + s_trans[STOP_TAG * KK + __ldg(tg + lenA - 1)];
                g_cf[bA] = CintA;
            }
        } else if (lane == 0) g_cb[bA] = CintA;
        {
            int prev = 0;
            if (lane == 0) {
                __threadfence();
                prev = atomicAdd(&g_flag[bA], 1);
            }
            prev = __shfl_sync(~0u, prev, 0);
            if (prev == 1) COMBINE(bA);
        }

        // epilogue chain B
        if (hasB) {
            if (is_fwd) {
                const int* tg = tags + bB * TT;
                float g = 0.0f;
                for (int q = lane; q < lenB; q += 32) {
                    int nxt = __ldg(tg + q);
                    int prv = (q == 0) ? START_TAG : __ldg(tg + q - 1);
                    g += s_trans[nxt * KK + prv] + __ldg(fbB + (long long)q * FS + nxt);
                }
                #pragma unroll
                for (int o = 16; o; o >>= 1) g += __shfl_xor_sync(~0u, g, o);
                if (lane == 0) {
                    g_gold[bB] = g + s_trans[STOP_TAG * KK + __ldg(tg + lenB - 1)];
                    g_cf[bB] = CintB;
                }
            } else if (lane == 0) g_cb[bB] = CintB;
            int prev = 0;
            if (lane == 0) {
                __threadfence();
                prev = atomicAdd(&g_flag[bB], 1);
            }
            prev = __shfl_sync(~0u, prev, 0);
            if (prev == 1) COMBINE(bB);
        }
    }
}

extern "C" void kernel_launch(void* const* d_in, const int* in_sizes, int n_in,
                              void* d_out, int out_size) {
    const float* feats   = (const float*)d_in[0];
    const float* trans   = (const float*)d_in[1];
    const int*   tags    = (const int*)d_in[2];
    const int*   lengths = (const int*)d_in[3];
    perm_kernel<<<2, 512>>>(lengths);
    crf_kernel<<<NBLKW, 128>>>(feats, trans, tags, lengths, (float*)d_out);
}

// round 16
// speedup vs baseline: 1.2206x; 1.2206x over previous
#include <cuda_runtime.h>

// CRF loss, T=512, B=1024, K=48. R16 = R11's exact worker (fwd/bwd split,
// LPT queues, linear-space recursion, smem ping-pong {P_2i,P_2i+1}, 12
// broadcast LDS.128 + 48 fma.rn.f32x2 / 8 accumulators, exact power-of-2
// renorm every 2 steps folded into ex2) at 296 blocks x 160 threads:
// 10 warps/SM (2.5/SMSP), reg cap 204 > natural 188 (no spills), 1480
// workers for 2048 jobs -> critical warp ~1 long job instead of 2.
// Direction = global warp parity (740 fwd / 740 bwd).

#define TT 512
#define BB 1024
#define KK 48
#define NBLKW 296
#define NWPB 5
#define START_TAG 46
#define STOP_TAG  47
#define LN2F  0.6931471805599453f
#define LOG2E 1.4426950408889634f
#define PFD 6

__device__ float g_partial[BB];
__device__ float g_fwdv[BB * KK];
__device__ float g_bwdv[BB * KK];
__device__ float g_gold[BB];
__device__ int   g_cf[BB];
__device__ int   g_cb[BB];
__device__ int   g_flag[BB];
__device__ int   g_order[BB];      // rank -> batch (longest first)
__device__ int   g_next_f, g_next_b, g_done;

__device__ __forceinline__ unsigned long long pack2(float lo, float hi) {
    unsigned long long r;
    asm("mov.b64 %0, {%1, %2};" : "=l"(r) : "f"(lo), "f"(hi));
    return r;
}
__device__ __forceinline__ void unpack2(unsigned long long v, float& lo, float& hi) {
    asm("mov.b64 {%0, %1}, %2;" : "=f"(lo), "=f"(hi) : "l"(v));
}
__device__ __forceinline__ unsigned long long fma2(unsigned long long a,
                                                   unsigned long long b,
                                                   unsigned long long c) {
    unsigned long long d;
    asm("fma.rn.f32x2 %0, %1, %2, %3;" : "=l"(d) : "l"(a), "l"(b), "l"(c));
    return d;
}
__device__ __forceinline__ unsigned long long add2(unsigned long long a,
                                                   unsigned long long b) {
    unsigned long long d;
    asm("add.rn.f32x2 %0, %1, %2;" : "=l"(d) : "l"(a), "l"(b));
    return d;
}
__device__ __forceinline__ float ex2f(float x) {
    float r;
    asm("ex2.approx.f32 %0, %1;" : "=f"(r) : "f"(x));
    return r;
}

// ---------- pre-pass: longest-first rank + counter/flag reset --------------
__global__ void perm_kernel(const int* __restrict__ lengths) {
    __shared__ int s_len[BB];
    const int tid = threadIdx.x;
    const int b = blockIdx.x * 512 + tid;
    s_len[tid] = lengths[tid];
    s_len[tid + 512] = lengths[tid + 512];
    __syncthreads();

    const int lb = s_len[b];
    int k = 0;
    #pragma unroll 8
    for (int j = 0; j < BB; j++) {
        int lj = s_len[j];
        k += (lj > lb) || (lj == lb && j < b);
    }
    g_order[k] = b;
    g_flag[b] = 0;
    if (b == 0) { g_next_f = 0; g_next_b = 0; g_done = 0; }
}

// ---------- one recursion step (R8/R11 body) -------------------------------
#define STEP(PIN, POUT, FC, RENORM)                                          \
    do {                                                                     \
        const ulonglong2* pv = (const ulonglong2*)(PIN);                     \
        ulonglong2 e0 = pv[0];                                               \
        unsigned long long c0 = fma2(e0.x, etp0[0], 0ull);                   \
        unsigned long long c2 = fma2(e0.y, etp0[1], 0ull);                   \
        unsigned long long c4 = fma2(e0.x, etp1[0], 0ull);                   \
        unsigned long long c6 = fma2(e0.y, etp1[1], 0ull);                   \
        unsigned long long c1 = 0ull, c3 = 0ull, c5 = 0ull, c7 = 0ull;       \
        _Pragma("unroll")                                                    \
        for (int q = 1; q < 12; q++) {                                       \
            ulonglong2 e = pv[q];                                            \
            if (q & 1) {                                                     \
                c1 = fma2(e.x, etp0[2*q],     c1);                           \
                c3 = fma2(e.y, etp0[2*q + 1], c3);                           \
                c5 = fma2(e.x, etp1[2*q],     c5);                           \
                c7 = fma2(e.y, etp1[2*q + 1], c7);                           \
            } else {                                                         \
                c0 = fma2(e.x, etp0[2*q],     c0);                           \
                c2 = fma2(e.y, etp0[2*q + 1], c2);                           \
                c4 = fma2(e.x, etp1[2*q],     c4);                           \
                c6 = fma2(e.y, etp1[2*q + 1], c6);                           \
            }                                                                \
        }                                                                    \
        unsigned long long sum0 = add2(add2(c0, c1), add2(c2, c3));          \
        unsigned long long sum1 = add2(add2(c4, c5), add2(c6, c7));          \
        float fpe = 0.0f;                                                    \
        if (RENORM) {                                                        \
            unsigned int pexp = ((unsigned)e0.x) >> 23;                      \
            int pe = (pexp - 1u < 254u) ? (int)pexp - 127 : 0;               \
            Cint += pe;                                                      \
            fpe = (float)(-pe);                                              \
        }                                                                    \
        float m0 = ex2f(fmaf((FC).x, LOG2E, fpe));                           \
        float m1 = ex2f(fmaf((FC).y, LOG2E, fpe));                           \
        float l0, h0, l1, h1;                                                \
        unpack2(sum0, l0, h0);                                               \
        unpack2(sum1, l1, h1);                                               \
        (POUT)[lane] = make_float2((l0 + h0) * m0, (l1 + h1) * m1);          \
    } while (0)

#define RUNLOOP(NSTEPS)                                                      \
    do {                                                                     \
        int t = 0;                                                           \
        _Pragma("unroll 1")                                                  \
        while (t + 1 < (NSTEPS)) {                                           \
            {                                                                \
                float2 fc = r1;                                              \
                r1 = r2; r2 = r3; r3 = r4; r4 = r5; r5 = r6;                 \
                r6 = (t < pre) ? __ldg(pf) : make_float2(0.0f, 0.0f);        \
                pf += pstep;                                                 \
                STEP(s_p[0], s_p[1], fc, true);                              \
            }                                                                \
            __syncwarp();                                                    \
            {                                                                \
                float2 fc = r1;                                              \
                r1 = r2; r2 = r3; r3 = r4; r4 = r5; r5 = r6;                 \
                r6 = (t + 1 < pre) ? __ldg(pf) : make_float2(0.0f, 0.0f);    \
                pf += pstep;                                                 \
                STEP(s_p[1], s_p[0], fc, false);                             \
            }                                                                \
            __syncwarp();                                                    \
            t += 2;                                                          \
        }                                                                    \
        if (t < (NSTEPS)) {                                                  \
            float2 fc = r1;                                                  \
            STEP(s_p[0], s_p[1], fc, true);                                  \
            __syncwarp();                                                    \
        }                                                                    \
    } while (0)

// second finisher: combine halves; last batch -> deterministic final sum
#define COMBINE(BATCH)                                                       \
    do {                                                                     \
        __threadfence();                                                     \
        float v = 0.0f;                                                      \
        if (act) {                                                           \
            float2 pfv = *(const float2*)&g_fwdv[(BATCH) * KK + sc];         \
            float2 bbv = *(const float2*)&g_bwdv[(BATCH) * KK + sc];         \
            v = pfv.x * bbv.x + pfv.y * bbv.y;                               \
        }                                                                    \
        _Pragma("unroll")                                                    \
        for (int o = 16; o; o >>= 1) v += __shfl_xor_sync(~0u, v, o);        \
        float logz = (float)(g_cf[BATCH] + g_cb[BATCH]) * LN2F + __logf(v);  \
        int l2 = 0;                                                          \
        if (lane == 0) {                                                     \
            g_partial[BATCH] = logz - g_gold[BATCH];                         \
            __threadfence();                                                 \
            int p2 = atomicAdd(&g_done, 1);                                  \
            l2 = (p2 == BB - 1);                                             \
        }                                                                    \
        l2 = __shfl_sync(~0u, l2, 0);                                        \
        if (l2) {                                                            \
            __threadfence();                                                 \
            float a = 0.0f;                                                  \
            _Pragma("unroll")                                                \
            for (int i = 0; i < BB / 32; i++)                                \
                a += g_partial[lane + i * 32];                               \
            _Pragma("unroll")                                                \
            for (int o = 16; o; o >>= 1) a += __shfl_xor_sync(~0u, a, o);    \
            if (lane == 0) out[0] = a;                                       \
        }                                                                    \
    } while (0)

__global__ void __launch_bounds__(160, 2) crf_kernel(
    const float* __restrict__ feats,
    const float* __restrict__ trans,
    const int*   __restrict__ tags,
    const int*   __restrict__ lengths,
    float*       __restrict__ out)
{
    __shared__ __align__(16) float2 s_pw[NWPB][2][32];
    __shared__ float s_trans[KK * KK];

    const int tid  = threadIdx.x;
    const int wid  = tid >> 5;
    const int lane = tid & 31;
    const bool act = (lane < 24);
    const int sc = act ? 2 * lane : 44;
    const int s0 = sc, s1 = sc + 1;
    const bool is_fwd = (((blockIdx.x * NWPB + wid) & 1) == 0);

    for (int i = tid; i < KK * KK; i += 160) s_trans[i] = trans[i];
    __syncthreads();

    float2 (*s_p)[32] = s_pw[wid];

    // weight tables: fwd = rows of exp(T); bwd = columns (E^T rows)
    unsigned long long etp0[24], etp1[24];
    #pragma unroll
    for (int i = 0; i < 24; i++) {
        if (is_fwd) {
            etp0[i] = pack2(__expf(s_trans[s0 * KK + 2*i]),
                            __expf(s_trans[s0 * KK + 2*i + 1]));
            etp1[i] = pack2(__expf(s_trans[s1 * KK + 2*i]),
                            __expf(s_trans[s1 * KK + 2*i + 1]));
        } else {
            etp0[i] = pack2(__expf(s_trans[(2*i) * KK + s0]),
                            __expf(s_trans[(2*i + 1) * KK + s0]));
            etp1[i] = pack2(__expf(s_trans[(2*i) * KK + s1]),
                            __expf(s_trans[(2*i + 1) * KK + s1]));
        }
    }
    const float st0 = __expf(s_trans[STOP_TAG * KK + s0]);
    const float st1 = __expf(s_trans[STOP_TAG * KK + s1]);
    const size_t FS = (size_t)BB * KK;
    const long long pstep = (long long)(FS / 2) * (is_fwd ? 1 : -1);
    int* qn = is_fwd ? &g_next_f : &g_next_b;

    if (is_fwd) {
        for (;;) {
            int j = 0;
            if (lane == 0) j = atomicAdd(qn, 1);
            j = __shfl_sync(~0u, j, 0);
            if (j >= BB) break;
            const int b   = __ldg(&g_order[j]);
            const int len = __ldg(lengths + b);
            const int m   = len >> 1;              // forward covers t in [0,m)
            const float* fb = feats + b * KK;

            s_p[0][lane] = (lane == 23) ? make_float2(1.0f, 0.0f)
                                        : make_float2(0.0f, 0.0f);  // START
            s_p[1][lane] = make_float2(0.0f, 0.0f);

            float2 r1, r2 = {0,0}, r3 = {0,0}, r4 = {0,0}, r5 = {0,0}, r6 = {0,0};
            r1 = __ldg((const float2*)(fb + sc));  // t=0 (in-bounds: len>=1)
            if (1 < m) r2 = __ldg((const float2*)(fb + 1 * FS + sc));
            if (2 < m) r3 = __ldg((const float2*)(fb + 2 * FS + sc));
            if (3 < m) r4 = __ldg((const float2*)(fb + 3 * FS + sc));
            if (4 < m) r5 = __ldg((const float2*)(fb + 4 * FS + sc));
            if (5 < m) r6 = __ldg((const float2*)(fb + 5 * FS + sc));
            const float2* pf = (const float2*)(fb + sc) + (long long)PFD * (FS / 2);
            const int pre = m - PFD;
            int Cint = 0;
            __syncwarp();

            RUNLOOP(m);

            if (act)
                *(float2*)&g_fwdv[b * KK + sc] = s_p[m & 1][lane];

            // gold score (full sequence)
            const int* tg = tags + b * TT;
            float g = 0.0f;
            for (int q = lane; q < len; q += 32) {
                int nxt = __ldg(tg + q);
                int prv = (q == 0) ? START_TAG : __ldg(tg + q - 1);
                g += s_trans[nxt * KK + prv] + __ldg(fb + (size_t)q * FS + nxt);
            }
            #pragma unroll
            for (int o = 16; o; o >>= 1) g += __shfl_xor_sync(~0u, g, o);

            int prev = 0;
            if (lane == 0) {
                g_gold[b] = g + s_trans[STOP_TAG * KK + __ldg(tg + len - 1)];
                g_cf[b] = Cint;
                __threadfence();
                prev = atomicAdd(&g_flag[b], 1);
            }
            prev = __shfl_sync(~0u, prev, 0);
            if (prev == 1) COMBINE(b);
        }
    } else {
        for (;;) {
            int j = 0;
            if (lane == 0) j = atomicAdd(qn, 1);
            j = __shfl_sync(~0u, j, 0);
            if (j >= BB) break;
            const int b   = __ldg(&g_order[j]);
            const int len = __ldg(lengths + b);
            const int m   = len >> 1;
            const int Ksteps = len - m;            // >= 1
            const float* fb = feats + b * KK;

            // init: W_{len-1} = ef_{len-1} (.) exp(trans[STOP, :])
            float2 f0 = __ldg((const float2*)(fb + (size_t)(len - 1) * FS + sc));
            s_p[0][lane] = make_float2(st0 * ex2f(f0.x * LOG2E),
                                       st1 * ex2f(f0.y * LOG2E));
            s_p[1][lane] = make_float2(0.0f, 0.0f);

            // descending prefetch: load i consumes feats[len-2-i], valid i<Ksteps-1
            float2 r1 = {0,0}, r2 = {0,0}, r3 = {0,0}, r4 = {0,0}, r5 = {0,0}, r6 = {0,0};
            const float2* fp2 = (const float2*)(fb + sc);
            if (0 < Ksteps - 1) r1 = __ldg(fp2 + (long long)(len - 2) * (FS / 2));
            if (1 < Ksteps - 1) r2 = __ldg(fp2 + (long long)(len - 3) * (FS / 2));
            if (2 < Ksteps - 1) r3 = __ldg(fp2 + (long long)(len - 4) * (FS / 2));
            if (3 < Ksteps - 1) r4 = __ldg(fp2 + (long long)(len - 5) * (FS / 2));
            if (4 < Ksteps - 1) r5 = __ldg(fp2 + (long long)(len - 6) * (FS / 2));
            if (5 < Ksteps - 1) r6 = __ldg(fp2 + (long long)(len - 7) * (FS / 2));
            const float2* pf = fp2 + (long long)(len - 2 - PFD) * (long long)(FS / 2);
            const int pre = Ksteps - 1 - PFD;
            int Cint = 0;
            __syncwarp();

            RUNLOOP(Ksteps);                       // last step fc=0 -> ef=1

            if (act)
                *(float2*)&g_bwdv[b * KK + sc] = s_p[Ksteps & 1][lane];

            int prev = 0;
            if (lane == 0) {
                g_cb[b] = Cint;
                __threadfence();
                prev = atomicAdd(&g_flag[b], 1);
            }
            prev = __shfl_sync(~0u, prev, 0);
            if (prev == 1) COMBINE(b);
        }
    }
}

extern "C" void kernel_launch(void* const* d_in, const int* in_sizes, int n_in,
                              void* d_out, int out_size) {
    const float* feats   = (const float*)d_in[0];
    const float* trans   = (const float*)d_in[1];
    const int*   tags    = (const int*)d_in[2];
    const int*   lengths = (const int*)d_in[3];
    perm_kernel<<<2, 512>>>(lengths);
    crf_kernel<<<NBLKW, 160>>>(feats, trans, tags, lengths, (float*)d_out);
}

// round 17
// speedup vs baseline: 1.6866x; 1.3818x over previous
#include <cuda_runtime.h>

// CRF loss, T=512, B=1024, K=48. R17 = R11 verbatim (fwd/bwd split, LPT
// queues, 296x128 at 2 blocks/SM, natural regs ~188) with two strictly
// instruction-reducing body edits: (1) exact power-of-2 renorm every 4 steps
// instead of 2 (range-safe: 3 un-renormed steps grow P by <= ~7e16, fp32-
// safe; renorm self-corrects), (2) mainloop unrolled x4 over the ping-pong.

#define TT 512
#define BB 1024
#define KK 48
#define NBLKW 296
#define START_TAG 46
#define STOP_TAG  47
#define LN2F  0.6931471805599453f
#define LOG2E 1.4426950408889634f
#define PFD 6

__device__ float g_partial[BB];
__device__ float g_fwdv[BB * KK];
__device__ float g_bwdv[BB * KK];
__device__ float g_gold[BB];
__device__ int   g_cf[BB];
__device__ int   g_cb[BB];
__device__ int   g_flag[BB];
__device__ int   g_order[BB];      // rank -> batch (longest first)
__device__ int   g_next_f, g_next_b, g_done;

__device__ __forceinline__ unsigned long long pack2(float lo, float hi) {
    unsigned long long r;
    asm("mov.b64 %0, {%1, %2};" : "=l"(r) : "f"(lo), "f"(hi));
    return r;
}
__device__ __forceinline__ void unpack2(unsigned long long v, float& lo, float& hi) {
    asm("mov.b64 {%0, %1}, %2;" : "=f"(lo), "=f"(hi) : "l"(v));
}
__device__ __forceinline__ unsigned long long fma2(unsigned long long a,
                                                   unsigned long long b,
                                                   unsigned long long c) {
    unsigned long long d;
    asm("fma.rn.f32x2 %0, %1, %2, %3;" : "=l"(d) : "l"(a), "l"(b), "l"(c));
    return d;
}
__device__ __forceinline__ unsigned long long add2(unsigned long long a,
                                                   unsigned long long b) {
    unsigned long long d;
    asm("add.rn.f32x2 %0, %1, %2;" : "=l"(d) : "l"(a), "l"(b));
    return d;
}
__device__ __forceinline__ float ex2f(float x) {
    float r;
    asm("ex2.approx.f32 %0, %1;" : "=f"(r) : "f"(x));
    return r;
}

// ---------- pre-pass: longest-first rank + counter/flag reset --------------
__global__ void perm_kernel(const int* __restrict__ lengths) {
    __shared__ int s_len[BB];
    const int tid = threadIdx.x;
    const int b = blockIdx.x * 512 + tid;
    s_len[tid] = lengths[tid];
    s_len[tid + 512] = lengths[tid + 512];
    __syncthreads();

    const int lb = s_len[b];
    int k = 0;
    #pragma unroll 8
    for (int j = 0; j < BB; j++) {
        int lj = s_len[j];
        k += (lj > lb) || (lj == lb && j < b);
    }
    g_order[k] = b;
    g_flag[b] = 0;
    if (b == 0) { g_next_f = 0; g_next_b = 0; g_done = 0; }
}

// ---------- one recursion step ---------------------------------------------
#define STEP(PIN, POUT, FC, RENORM)                                          \
    do {                                                                     \
        const ulonglong2* pv = (const ulonglong2*)(PIN);                     \
        ulonglong2 e0 = pv[0];                                               \
        unsigned long long c0 = fma2(e0.x, etp0[0], 0ull);                   \
        unsigned long long c2 = fma2(e0.y, etp0[1], 0ull);                   \
        unsigned long long c4 = fma2(e0.x, etp1[0], 0ull);                   \
        unsigned long long c6 = fma2(e0.y, etp1[1], 0ull);                   \
        unsigned long long c1 = 0ull, c3 = 0ull, c5 = 0ull, c7 = 0ull;       \
        _Pragma("unroll")                                                    \
        for (int q = 1; q < 12; q++) {                                       \
            ulonglong2 e = pv[q];                                            \
            if (q & 1) {                                                     \
                c1 = fma2(e.x, etp0[2*q],     c1);                           \
                c3 = fma2(e.y, etp0[2*q + 1], c3);                           \
                c5 = fma2(e.x, etp1[2*q],     c5);                           \
                c7 = fma2(e.y, etp1[2*q + 1], c7);                           \
            } else {                                                         \
                c0 = fma2(e.x, etp0[2*q],     c0);                           \
                c2 = fma2(e.y, etp0[2*q + 1], c2);                           \
                c4 = fma2(e.x, etp1[2*q],     c4);                           \
                c6 = fma2(e.y, etp1[2*q + 1], c6);                           \
            }                                                                \
        }                                                                    \
        unsigned long long sum0 = add2(add2(c0, c1), add2(c2, c3));          \
        unsigned long long sum1 = add2(add2(c4, c5), add2(c6, c7));          \
        float fpe = 0.0f;                                                    \
        if (RENORM) {                                                        \
            unsigned int pexp = ((unsigned)e0.x) >> 23;                      \
            int pe = (pexp - 1u < 254u) ? (int)pexp - 127 : 0;               \
            Cint += pe;                                                      \
            fpe = (float)(-pe);                                              \
        }                                                                    \
        float m0 = ex2f(fmaf((FC).x, LOG2E, fpe));                           \
        float m1 = ex2f(fmaf((FC).y, LOG2E, fpe));                           \
        float l0, h0, l1, h1;                                                \
        unpack2(sum0, l0, h0);                                               \
        unpack2(sum1, l1, h1);                                               \
        (POUT)[lane] = make_float2((l0 + h0) * m0, (l1 + h1) * m1);          \
    } while (0)

// one step incl. prefetch advance; OFF = step offset within unrolled group
#define FULLSTEP(PIN, POUT, OFF, RENORM)                                     \
    do {                                                                     \
        float2 fc = r1;                                                      \
        r1 = r2; r2 = r3; r3 = r4; r4 = r5; r5 = r6;                         \
        r6 = (t + (OFF) < pre) ? __ldg(pf) : make_float2(0.0f, 0.0f);        \
        pf += pstep;                                                         \
        STEP(PIN, POUT, fc, RENORM);                                         \
    } while (0)

// run N steps over the s_p ping-pong; result lands in s_p[N & 1].
// Renorm on the first step of each 4-group (exact, self-correcting).
#define RUNLOOP(NSTEPS)                                                      \
    do {                                                                     \
        int t = 0;                                                           \
        _Pragma("unroll 1")                                                  \
        while (t + 3 < (NSTEPS)) {                                           \
            FULLSTEP(s_p[0], s_p[1], 0, true);                               \
            __syncwarp();                                                    \
            FULLSTEP(s_p[1], s_p[0], 1, false);                              \
            __syncwarp();                                                    \
            FULLSTEP(s_p[0], s_p[1], 2, false);                              \
            __syncwarp();                                                    \
            FULLSTEP(s_p[1], s_p[0], 3, false);                              \
            __syncwarp();                                                    \
            t += 4;                                                          \
        }                                                                    \
        _Pragma("unroll 1")                                                  \
        while (t + 1 < (NSTEPS)) {                                           \
            FULLSTEP(s_p[0], s_p[1], 0, true);                               \
            __syncwarp();                                                    \
            FULLSTEP(s_p[1], s_p[0], 1, false);                              \
            __syncwarp();                                                    \
            t += 2;                                                          \
        }                                                                    \
        if (t < (NSTEPS)) {                                                  \
            FULLSTEP(s_p[0], s_p[1], 0, true);                               \
            __syncwarp();                                                    \
        }                                                                    \
    } while (0)

// second finisher: combine halves; last batch -> deterministic final sum
#define COMBINE(BATCH)                                                       \
    do {                                                                     \
        __threadfence();                                                     \
        float v = 0.0f;                                                      \
        if (act) {                                                           \
            float2 pfv = *(const float2*)&g_fwdv[(BATCH) * KK + sc];         \
            float2 bbv = *(const float2*)&g_bwdv[(BATCH) * KK + sc];         \
            v = pfv.x * bbv.x + pfv.y * bbv.y;                               \
        }                                                                    \
        _Pragma("unroll")                                                    \
        for (int o = 16; o; o >>= 1) v += __shfl_xor_sync(~0u, v, o);        \
        float logz = (float)(g_cf[BATCH] + g_cb[BATCH]) * LN2F + __logf(v);  \
        int l2 = 0;                                                          \
        if (lane == 0) {                                                     \
            g_partial[BATCH] = logz - g_gold[BATCH];                         \
            __threadfence();                                                 \
            int p2 = atomicAdd(&g_done, 1);                                  \
            l2 = (p2 == BB - 1);                                             \
        }                                                                    \
        l2 = __shfl_sync(~0u, l2, 0);                                        \
        if (l2) {                                                            \
            __threadfence();                                                 \
            float a = 0.0f;                                                  \
            _Pragma("unroll")                                                \
            for (int i = 0; i < BB / 32; i++)                                \
                a += g_partial[lane + i * 32];                               \
            _Pragma("unroll")                                                \
            for (int o = 16; o; o >>= 1) a += __shfl_xor_sync(~0u, a, o);    \
            if (lane == 0) out[0] = a;                                       \
        }                                                                    \
    } while (0)

__global__ void __launch_bounds__(128, 2) crf_kernel(
    const float* __restrict__ feats,
    const float* __restrict__ trans,
    const int*   __restrict__ tags,
    const int*   __restrict__ lengths,
    float*       __restrict__ out)
{
    __shared__ __align__(16) float2 s_pw[4][2][32];
    __shared__ float s_trans[KK * KK];

    const int tid  = threadIdx.x;
    const int wid  = tid >> 5;
    const int lane = tid & 31;
    const bool act = (lane < 24);
    const int sc = act ? 2 * lane : 44;
    const int s0 = sc, s1 = sc + 1;
    const bool is_fwd = (wid < 2);

    for (int i = tid; i < KK * KK; i += 128) s_trans[i] = trans[i];
    __syncthreads();

    float2 (*s_p)[32] = s_pw[wid];

    // weight tables: fwd = rows of exp(T); bwd = columns (E^T rows)
    unsigned long long etp0[24], etp1[24];
    #pragma unroll
    for (int i = 0; i < 24; i++) {
        if (is_fwd) {
            etp0[i] = pack2(__expf(s_trans[s0 * KK + 2*i]),
                            __expf(s_trans[s0 * KK + 2*i + 1]));
            etp1[i] = pack2(__expf(s_trans[s1 * KK + 2*i]),
                            __expf(s_trans[s1 * KK + 2*i + 1]));
        } else {
            etp0[i] = pack2(__expf(s_trans[(2*i) * KK + s0]),
                            __expf(s_trans[(2*i + 1) * KK + s0]));
            etp1[i] = pack2(__expf(s_trans[(2*i) * KK + s1]),
                            __expf(s_trans[(2*i + 1) * KK + s1]));
        }
    }
    const float st0 = __expf(s_trans[STOP_TAG * KK + s0]);
    const float st1 = __expf(s_trans[STOP_TAG * KK + s1]);
    const size_t FS = (size_t)BB * KK;
    const long long pstep = (long long)(FS / 2) * (is_fwd ? 1 : -1);
    int* qn = is_fwd ? &g_next_f : &g_next_b;

    if (is_fwd) {
        for (;;) {
            int j = 0;
            if (lane == 0) j = atomicAdd(qn, 1);
            j = __shfl_sync(~0u, j, 0);
            if (j >= BB) break;
            const int b   = __ldg(&g_order[j]);
            const int len = __ldg(lengths + b);
            const int m   = len >> 1;              // forward covers t in [0,m)
            const float* fb = feats + b * KK;

            s_p[0][lane] = (lane == 23) ? make_float2(1.0f, 0.0f)
                                        : make_float2(0.0f, 0.0f);  // START
            s_p[1][lane] = make_float2(0.0f, 0.0f);

            float2 r1, r2 = {0,0}, r3 = {0,0}, r4 = {0,0}, r5 = {0,0}, r6 = {0,0};
            r1 = __ldg((const float2*)(fb + sc));  // t=0 (in-bounds: len>=1)
            if (1 < m) r2 = __ldg((const float2*)(fb + 1 * FS + sc));
            if (2 < m) r3 = __ldg((const float2*)(fb + 2 * FS + sc));
            if (3 < m) r4 = __ldg((const float2*)(fb + 3 * FS + sc));
            if (4 < m) r5 = __ldg((const float2*)(fb + 4 * FS + sc));
            if (5 < m) r6 = __ldg((const float2*)(fb + 5 * FS + sc));
            const float2* pf = (const float2*)(fb + sc) + (long long)PFD * (FS / 2);
            const int pre = m - PFD;
            int Cint = 0;
            __syncwarp();

            RUNLOOP(m);

            if (act)
                *(float2*)&g_fwdv[b * KK + sc] = s_p[m & 1][lane];

            // gold score (full sequence)
            const int* tg = tags + b * TT;
            float g = 0.0f;
            for (int q = lane; q < len; q += 32) {
                int nxt = __ldg(tg + q);
                int prv = (q == 0) ? START_TAG : __ldg(tg + q - 1);
                g += s_trans[nxt * KK + prv] + __ldg(fb + (size_t)q * FS + nxt);
            }
            #pragma unroll
            for (int o = 16; o; o >>= 1) g += __shfl_xor_sync(~0u, g, o);

            int prev = 0;
            if (lane == 0) {
                g_gold[b] = g + s_trans[STOP_TAG * KK + __ldg(tg + len - 1)];
                g_cf[b] = Cint;
                __threadfence();
                prev = atomicAdd(&g_flag[b], 1);
            }
            prev = __shfl_sync(~0u, prev, 0);
            if (prev == 1) COMBINE(b);
        }
    } else {
        for (;;) {
            int j = 0;
            if (lane == 0) j = atomicAdd(qn, 1);
            j = __shfl_sync(~0u, j, 0);
            if (j >= BB) break;
            const int b   = __ldg(&g_order[j]);
            const int len = __ldg(lengths + b);
            const int m   = len >> 1;
            const int Ksteps = len - m;            // >= 1
            const float* fb = feats + b * KK;

            // init: W_{len-1} = ef_{len-1} (.) exp(trans[STOP, :])
            float2 f0 = __ldg((const float2*)(fb + (size_t)(len - 1) * FS + sc));
            s_p[0][lane] = make_float2(st0 * ex2f(f0.x * LOG2E),
                                       st1 * ex2f(f0.y * LOG2E));
            s_p[1][lane] = make_float2(0.0f, 0.0f);

            // descending prefetch: load i consumes feats[len-2-i], valid i<Ksteps-1
            float2 r1 = {0,0}, r2 = {0,0}, r3 = {0,0}, r4 = {0,0}, r5 = {0,0}, r6 = {0,0};
            const float2* fp2 = (const float2*)(fb + sc);
            if (0 < Ksteps - 1) r1 = __ldg(fp2 + (long long)(len - 2) * (FS / 2));
            if (1 < Ksteps - 1) r2 = __ldg(fp2 + (long long)(len - 3) * (FS / 2));
            if (2 < Ksteps - 1) r3 = __ldg(fp2 + (long long)(len - 4) * (FS / 2));
            if (3 < Ksteps - 1) r4 = __ldg(fp2 + (long long)(len - 5) * (FS / 2));
            if (4 < Ksteps - 1) r5 = __ldg(fp2 + (long long)(len - 6) * (FS / 2));
            if (5 < Ksteps - 1) r6 = __ldg(fp2 + (long long)(len - 7) * (FS / 2));
            const float2* pf = fp2 + (long long)(len - 2 - PFD) * (long long)(FS / 2);
            const int pre = Ksteps - 1 - PFD;
            int Cint = 0;
            __syncwarp();

            RUNLOOP(Ksteps);                       // last step fc=0 -> ef=1

            if (act)
                *(float2*)&g_bwdv[b * KK + sc] = s_p[Ksteps & 1][lane];

            int prev = 0;
            if (lane == 0) {
                g_cb[b] = Cint;
                __threadfence();
                prev = atomicAdd(&g_flag[b], 1);
            }
            prev = __shfl_sync(~0u, prev, 0);
            if (prev == 1) COMBINE(b);
        }
    }
}

extern "C" void kernel_launch(void* const* d_in, const int* in_sizes, int n_in,
                              void* d_out, int out_size) {
    const float* feats   = (const float*)d_in[0];
    const float* trans   = (const float*)d_in[1];
    const int*   tags    = (const int*)d_in[2];
    const int*   lengths = (const int*)d_in[3];
    perm_kernel<<<2, 512>>>(lengths);
    crf_kernel<<<NBLKW, 128>>>(feats, trans, tags, lengths, (float*)d_out);
}